// round 14
// baseline (speedup 1.0000x reference)
#include <cuda_runtime.h>
#include <cuda_bf16.h>
#include <math.h>
#include <float.h>
#include <stdint.h>

#define NQ    1024
#define MP    100000
#define DIM   256
#define KTOP  7
#define QTILE 256
#define PTILE 128
#define NT    782            // ceil(100000/128)
#define NQB   (NQ / QTILE)   // 4
#define NPA   16             // phase-A tiles per qblock
#define NCHB  37             // phase-B slots per qblock (148 CTAs = one wave)
#define NSLOT (NCHB + NPA)   // 53
#define KC    12
#define TOPC  32
#define MPPAD (NT * PTILE)   // 100096
#define FB    2048

// ---------------- device scratch ----------------
__device__ float g_qn[NQ * DIM];
__device__ float g_eq[NQ];
__device__ float g_ieq[NQ];
__device__ float g_qts[NQ];
__device__ int   g_qsrc[NQ];
__device__ float g_pA[MPPAD];
__device__ float g_pB[MPPAD];
__device__ int   g_pidx[MPPAD];
__device__ unsigned int g_tmin[NT];
__device__ unsigned int g_tmax[NT];
__device__ int   g_hist[FB];
__device__ int   g_binoff[FB];
__device__ float g_s7s[NQB];
__device__ int   g_klist[NQB * NT];
__device__ int   g_kcnt[NQB];
__device__ __nv_bfloat16 g_qhi[NQ * DIM];
__device__ __nv_bfloat16 g_phi[(size_t)MPPAD * DIM];
__device__ float g_cv[(size_t)NQ * NSLOT * KC];
__device__ int   g_ci[(size_t)NQ * NSLOT * KC];   // ORIGINAL pool indices
__device__ int   g_topi[NQ * KTOP];

__device__ __forceinline__ bool better(float s1, int i1, float s2, int i2) {
    return (s1 > s2) || (s1 == s2 && i1 < i2);
}
__device__ __forceinline__ uint32_t smem_to_u32(const void* p) {
    uint32_t a;
    asm("{ .reg .u64 t; cvta.to.shared.u64 t, %1; cvt.u32.u64 %0, t; }" : "=r"(a) : "l"(p));
    return a;
}
__device__ __forceinline__ void ldsm_x4(uint32_t& r0, uint32_t& r1, uint32_t& r2, uint32_t& r3,
                                        uint32_t addr) {
    asm volatile("ldmatrix.sync.aligned.m8n8.x4.shared.b16 {%0,%1,%2,%3}, [%4];"
        : "=r"(r0), "=r"(r1), "=r"(r2), "=r"(r3) : "r"(addr));
}
__device__ __forceinline__ void mma16816(float* d, const uint32_t* a, uint32_t b0, uint32_t b1) {
    asm volatile("mma.sync.aligned.m16n8k16.row.col.f32.bf16.bf16.f32 "
        "{%0,%1,%2,%3}, {%4,%5,%6,%7}, {%8,%9}, {%0,%1,%2,%3};"
        : "+f"(d[0]), "+f"(d[1]), "+f"(d[2]), "+f"(d[3])
        : "r"(a[0]), "r"(a[1]), "r"(a[2]), "r"(a[3]), "r"(b0), "r"(b1));
}
#define CP_ASYNC16(dst, src) asm volatile("cp.async.cg.shared.global [%0], [%1], 16;" :: "r"(dst), "l"(src))
#define CP_COMMIT() asm volatile("cp.async.commit_group;" ::: "memory")
#define CP_WAIT0()  asm volatile("cp.async.wait_group 0;" ::: "memory")

// top-4 sorted insertion (hot path: one compare)
__device__ __forceinline__ void ins4(float s, int p,
                                     float& v0, int& i0, float& v1, int& i1,
                                     float& v2, int& i2, float& v3, int& i3) {
    if (better(s, p, v3, i3)) {
        if (better(s, p, v1, i1)) {
            v3 = v2; i3 = i2; v2 = v1; i2 = i1;
            if (better(s, p, v0, i0)) { v1 = v0; i1 = i0; v0 = s; i0 = p; }
            else { v1 = s; i1 = p; }
        } else {
            if (better(s, p, v2, i2)) { v3 = v2; i3 = i2; v2 = s; i2 = p; }
            else { v3 = s; i3 = p; }
        }
    }
}

__device__ __forceinline__ int phaseA_tile(int qBase, int j) {
    int rankj = qBase + 8 + 16 * j;
    return (int)(((long long)rankj * MP) / ((long long)NQ * PTILE));
}

// smem layout (QTILE=256 engine, bf16)
#define SOFF_A    0                  // 131072: A 256x256 bf16, swizzled 512B rows
#define SOFF_B0   131072             // 32768
#define SOFF_B1   163840             // 32768
#define SOFF_PAB  196608             // 2048: float2[2][128]
#define SMEM_TOTAL 198656

// ---------------- sort kernels ----------------
__global__ void zero_kernel() {
    int t = threadIdx.x;
    for (int i = t; i < FB; i += 1024) g_hist[i] = 0;
    for (int i = t; i < NT; i += 1024) { g_tmin[i] = 0xFFFFFFFFu; g_tmax[i] = 0u; }
}

__global__ void qsort_kernel(const float* __restrict__ qt) {
    __shared__ float tm[NQ];
    int i = threadIdx.x;
    tm[i] = qt[i];
    __syncthreads();
    float ti = tm[i];
    int rank = 0;
    for (int j = 0; j < NQ; j++) {
        float tj = tm[j];
        rank += (tj < ti) || (tj == ti && j < i);
    }
    g_qsrc[rank] = i;
    g_qts[rank]  = ti;
}

__global__ void hist_kernel(const float* __restrict__ pt) {
    int i = blockIdx.x * 1024 + threadIdx.x;
    if (i >= MP) return;
    int bin = min(FB - 1, (int)(pt[i] * (FB / 100.0f)));
    atomicAdd(&g_hist[bin], 1);
}

__global__ void scan_kernel() {
    __shared__ int sh[1024];
    int t = threadIdx.x;
    int a = g_hist[2 * t], b = g_hist[2 * t + 1];
    sh[t] = a + b;
    __syncthreads();
    for (int off = 1; off < 1024; off <<= 1) {
        int v = (t >= off) ? sh[t - off] : 0;
        __syncthreads();
        sh[t] += v;
        __syncthreads();
    }
    int ex = sh[t] - (a + b);
    g_binoff[2 * t]     = ex;
    g_binoff[2 * t + 1] = ex + a;
}

__global__ void scatter_kernel(const float* __restrict__ pt) {
    int i = blockIdx.x * 1024 + threadIdx.x;
    if (i >= MP) return;
    float t = pt[i];
    int bin = min(FB - 1, (int)(t * (FB / 100.0f)));
    int pos = atomicAdd(&g_binoff[bin], 1);
    g_pidx[pos] = i;
    int tile = pos >> 7;
    unsigned int u = __float_as_uint(t);
    atomicMin(&g_tmin[tile], u);
    atomicMax(&g_tmax[tile], u);
}

// ---------------- prep kernels ----------------
__global__ void prep_query_kernel(const float* __restrict__ qe,
                                  const float* __restrict__ lam) {
    int row  = blockIdx.x * 8 + (threadIdx.x >> 5);
    int lane = threadIdx.x & 31;
    if (row >= NQ) return;
    int orig = g_qsrc[row];
    const float4* src = (const float4*)(qe + (size_t)orig * DIM + lane * 8);
    float4 a = src[0], b = src[1];
    float ss = a.x*a.x + a.y*a.y + a.z*a.z + a.w*a.w
             + b.x*b.x + b.y*b.y + b.z*b.z + b.w*b.w;
    #pragma unroll
    for (int o = 16; o > 0; o >>= 1) ss += __shfl_xor_sync(0xffffffff, ss, o);
    float inv = 1.0f / fmaxf(sqrtf(ss), 1e-8f);
    float v[8] = {a.x*inv, a.y*inv, a.z*inv, a.w*inv, b.x*inv, b.y*inv, b.z*inv, b.w*inv};
    float4* dst = (float4*)(g_qn + row * DIM + lane * 8);
    dst[0] = make_float4(v[0], v[1], v[2], v[3]);
    dst[1] = make_float4(v[4], v[5], v[6], v[7]);
    __nv_bfloat16 hv[8];
    #pragma unroll
    for (int i = 0; i < 8; i++) hv[i] = __float2bfloat16(v[i]);
    *(uint4*)(g_qhi + row * DIM + lane * 8) = *(uint4*)hv;
    if (lane == 0) {
        float l = lam[0], t = g_qts[row];
        g_eq[row]  = expf(l * t);
        g_ieq[row] = expf(-l * t);
    }
}

__global__ void prep_pool_kernel(const float* __restrict__ pe,
                                 const float* __restrict__ pt,
                                 const float* __restrict__ lam) {
    int row  = blockIdx.x * 8 + (threadIdx.x >> 5);
    int lane = threadIdx.x & 31;
    if (row >= MPPAD) return;
    if (row >= MP) {
        *(uint4*)(g_phi + (size_t)row * DIM + lane * 8) = make_uint4(0, 0, 0, 0);
        if (lane == 0) { g_pA[row] = 0.f; g_pB[row] = 0.f; g_pidx[row] = MP; }
        return;
    }
    int orig = g_pidx[row];
    const float4* src = (const float4*)(pe + (size_t)orig * DIM + lane * 8);
    float4 a = src[0], b = src[1];
    float ss = a.x*a.x + a.y*a.y + a.z*a.z + a.w*a.w
             + b.x*b.x + b.y*b.y + b.z*b.z + b.w*b.w;
    #pragma unroll
    for (int o = 16; o > 0; o >>= 1) ss += __shfl_xor_sync(0xffffffff, ss, o);
    float v[8] = {a.x, a.y, a.z, a.w, b.x, b.y, b.z, b.w};
    __nv_bfloat16 hv[8];
    #pragma unroll
    for (int i = 0; i < 8; i++) hv[i] = __float2bfloat16(v[i]);
    *(uint4*)(g_phi + (size_t)row * DIM + lane * 8) = *(uint4*)hv;
    if (lane == 0) {
        float inv = 1.0f / fmaxf(sqrtf(ss), 1e-8f);
        float l = lam[0], t = pt[orig];
        g_pA[row] = inv * expf(-l * t);
        g_pB[row] = inv * expf(l * t);
    }
}

// ---------------- build balanced kept-tile list per qblock ----------------
__global__ void buildlist_kernel(const float* __restrict__ lam) {
    __shared__ unsigned char keep[NT];
    const int b = blockIdx.x, t = threadIdx.x;
    const float s7s = g_s7s[b];
    const float qlo = g_qts[b * QTILE], qhi = g_qts[b * QTILE + QTILE - 1];
    const float lv = lam[0];
    for (int i = t; i < NT; i += 256) {
        bool isA = false;
        #pragma unroll
        for (int j = 0; j < NPA; j++)
            if (i == phaseA_tile(b * QTILE, j)) isA = true;
        bool k = false;
        if (!isA) {
            float tmn = __uint_as_float(g_tmin[i]);
            float tmx = __uint_as_float(g_tmax[i]);
            float gap = fmaxf(0.f, fmaxf(qlo - tmx, tmn - qhi));
            k = (expf(-lv * gap) >= s7s);
        }
        keep[i] = k ? 1 : 0;
    }
    __syncthreads();
    if (t == 0) {
        int m = 0;
        for (int i = 0; i < NT; i++)
            if (keep[i]) g_klist[b * NT + m++] = i;
        g_kcnt[b] = m;
    }
}

// ---------------- MMA engine (phase 0 = A: one tile; phase 1 = B: list slice) ----------------
__global__ __launch_bounds__(512, 1)
void engine_kernel(int phase) {
    extern __shared__ char smem[];
    const uint32_t sb = smem_to_u32(smem);
    float2* spAB = (float2*)(smem + SOFF_PAB);   // [2][128]

    const int tid = threadIdx.x;
    const int wid = tid >> 5, lane = tid & 31;
    const int wq = wid >> 1, wp = wid & 1;       // 8q x 2p warps, warp tile 32q x 64p
    const int bi2 = blockIdx.x, b = blockIdx.y;
    const int qBase = b * QTILE;

    int m, base0 = 0, tA = 0, cslot;
    if (phase == 0) {
        tA = phaseA_tile(qBase, bi2);
        m = 1;
        cslot = NCHB + bi2;
    } else {
        int cnt = g_kcnt[b];
        base0 = (bi2 * cnt) / NCHB;
        m = ((bi2 + 1) * cnt) / NCHB - base0;
        cslot = bi2;
    }
    #define TILEOF(k_) ((phase == 0) ? tA : g_klist[b * NT + base0 + (k_)])

    if (m == 0) {
        if (tid < 256) {
            size_t base = ((size_t)(qBase + tid) * NSLOT + cslot) * KC;
            #pragma unroll
            for (int u = 0; u < KC; u++) { g_cv[base + u] = -FLT_MAX; g_ci[base + u] = MP; }
        }
        return;
    }

    // ---- load A once (256 rows x 512B bf16, swizzled): 2 threads/row ----
    {
        int row = tid >> 1, part = tid & 1;
        const uint4* asrc = (const uint4*)(g_qhi + (size_t)(qBase + row) * DIM) + part * 16;
        uint32_t arb = (uint32_t)row * 512;
        uint32_t xr0 = (uint32_t)(row & 7) << 4;
        #pragma unroll
        for (int g2 = 0; g2 < 16; g2++) {
            uint32_t kg = (uint32_t)(part * 16 + g2);
            *(uint4*)(smem + SOFF_A + arb + ((kg << 4) ^ xr0)) = asrc[g2];
        }
    }

    // per-thread row weights (4 rows)
    const int g = lane >> 2;
    float eqr[4], ieqr[4];
    #pragma unroll
    for (int mt = 0; mt < 2; mt++)
        #pragma unroll
        for (int h = 0; h < 2; h++) {
            int r = qBase + wq * 32 + mt * 16 + g + h * 8;
            eqr[mt * 2 + h]  = g_eq[r];
            ieqr[mt * 2 + h] = g_ieq[r];
        }

    // fragment addressing
    const int mh = (lane >> 4) & 1;
    const int mlow = (lane >> 3) & 1;
    const int lr = lane & 7;
    const uint32_t xr = (uint32_t)lr << 4;
    uint32_t aBase[2], bBase[4];
    #pragma unroll
    for (int mt = 0; mt < 2; mt++)
        aBase[mt] = sb + SOFF_A + (uint32_t)(wq * 32 + mt * 16 + mlow * 8 + lr) * 512;
    #pragma unroll
    for (int n16 = 0; n16 < 4; n16++)
        bBase[n16] = (uint32_t)(wp * 64 + n16 * 16 + mlow * 8 + lr) * 256;

    // bucket top-4 per (thread, row)
    float tv0[4], tv1[4], tv2[4], tv3[4];
    int   ti0[4], ti1[4], ti2[4], ti3[4];
    #pragma unroll
    for (int j = 0; j < 4; j++) {
        tv0[j] = tv1[j] = tv2[j] = tv3[j] = -FLT_MAX;
        ti0[j] = ti1[j] = ti2[j] = ti3[j] = 0x7fffffff;
    }

    // cp.async: 128p x 128k bf16 half-tile (32KB): 4 threads/row, 4 x 16B each
    const int brow = tid >> 2, bseg = tid & 3;
    const uint32_t brb = (uint32_t)brow * 256;
    const uint32_t bxr = (uint32_t)(brow & 7) << 4;
    #define ISSUE(t_, kh_) do { \
        const char* _src = (const char*)(g_phi + (size_t)((t_) * PTILE + brow) * DIM + (kh_) * 128 + bseg * 32); \
        uint32_t _dst = sb + ((kh_) ? SOFF_B1 : SOFF_B0); \
        _Pragma("unroll") \
        for (int _g = 0; _g < 4; _g++) { \
            uint32_t _kg = (uint32_t)(bseg * 4 + _g); \
            CP_ASYNC16(_dst + brb + ((_kg << 4) ^ bxr), _src + _g * 16); \
        } \
        CP_COMMIT(); \
    } while (0)

    ISSUE(TILEOF(0), 0);

    float d[2][8][4];

    #pragma unroll 1
    for (int i = 0; i < m; i++) {
        const int tile = TILEOF(i);
        const int pBase = tile * PTILE;
        #pragma unroll
        for (int mt = 0; mt < 2; mt++)
            #pragma unroll
            for (int n = 0; n < 8; n++)
                #pragma unroll
                for (int e = 0; e < 4; e++) d[mt][n][e] = 0.0f;

        #pragma unroll
        for (int c = 0; c < 2; c++) {
            const int s = 2 * i + c;
            CP_WAIT0();
            __syncthreads();
            if (c == 0 && tid < 128)
                spAB[(i & 1) * 128 + tid] = make_float2(g_pA[pBase + tid], g_pB[pBase + tid]);
            if (s + 1 < 2 * m) ISSUE(TILEOF((s + 1) >> 1), (s + 1) & 1);

            const uint32_t bbuf = sb + (c ? SOFF_B1 : SOFF_B0);
            #pragma unroll
            for (int kk = 0; kk < 8; kk++) {
                const int ks = c * 8 + kk;
                uint32_t a[2][4];
                uint32_t aoffk = ((uint32_t)((ks * 2 + mh) << 4)) ^ xr;
                ldsm_x4(a[0][0], a[0][1], a[0][2], a[0][3], aBase[0] + aoffk);
                ldsm_x4(a[1][0], a[1][1], a[1][2], a[1][3], aBase[1] + aoffk);
                uint32_t boffk = ((uint32_t)((kk * 2 + mh) << 4)) ^ xr;
                #pragma unroll
                for (int n16 = 0; n16 < 4; n16++) {
                    uint32_t b0, b1, b2, b3;
                    ldsm_x4(b0, b1, b2, b3, bbuf + bBase[n16] + boffk);
                    mma16816(d[0][n16 * 2 + 0], a[0], b0, b2);
                    mma16816(d[0][n16 * 2 + 1], a[0], b1, b3);
                    mma16816(d[1][n16 * 2 + 0], a[1], b0, b2);
                    mma16816(d[1][n16 * 2 + 1], a[1], b1, b3);
                }
            }
        }

        // ---- in-register epilogue: weight + bucket top-4 ----
        const float2* wab = spAB + (i & 1) * 128;
        #pragma unroll
        for (int n = 0; n < 8; n++) {
            int c0 = wp * 64 + n * 8 + (lane & 3) * 2;
            float4 w = *(const float4*)((const char*)wab + (size_t)c0 * 8);
            int p0 = pBase + c0;
            bool ok0 = (p0 < MP), ok1 = (p0 + 1 < MP);
            #pragma unroll
            for (int mt = 0; mt < 2; mt++) {
                const int j0 = mt * 2, j1 = mt * 2 + 1;
                float s00 = d[mt][n][0] * fminf(eqr[j0] * w.x, ieqr[j0] * w.y);
                float s01 = d[mt][n][1] * fminf(eqr[j0] * w.z, ieqr[j0] * w.w);
                float s10 = d[mt][n][2] * fminf(eqr[j1] * w.x, ieqr[j1] * w.y);
                float s11 = d[mt][n][3] * fminf(eqr[j1] * w.z, ieqr[j1] * w.w);
                if (ok0) {
                    ins4(s00, p0, tv0[j0], ti0[j0], tv1[j0], ti1[j0], tv2[j0], ti2[j0], tv3[j0], ti3[j0]);
                    ins4(s10, p0, tv0[j1], ti0[j1], tv1[j1], ti1[j1], tv2[j1], ti2[j1], tv3[j1], ti3[j1]);
                }
                if (ok1) {
                    ins4(s01, p0 + 1, tv0[j0], ti0[j0], tv1[j0], ti1[j0], tv2[j0], ti2[j0], tv3[j0], ti3[j0]);
                    ins4(s11, p0 + 1, tv0[j1], ti0[j1], tv1[j1], ti1[j1], tv2[j1], ti2[j1], tv3[j1], ti3[j1]);
                }
            }
        }
    }

    // ---- final merge: 8 buckets x 4 per row -> top-12, original indices ----
    __syncthreads();
    float2* mb = (float2*)(smem + SOFF_B0);   // [256 rows][8 slots][4] = 64KB
    const int slot = wp * 4 + (lane & 3);
    #pragma unroll
    for (int mt = 0; mt < 2; mt++)
        #pragma unroll
        for (int h = 0; h < 2; h++) {
            int r = wq * 32 + mt * 16 + g + h * 8;
            int j = mt * 2 + h;
            int base = (r * 8 + slot) * 4;
            mb[base + 0] = make_float2(tv0[j], __int_as_float(ti0[j]));
            mb[base + 1] = make_float2(tv1[j], __int_as_float(ti1[j]));
            mb[base + 2] = make_float2(tv2[j], __int_as_float(ti2[j]));
            mb[base + 3] = make_float2(tv3[j], __int_as_float(ti3[j]));
        }
    __syncthreads();
    if (tid < 256) {
        float bv[KC]; int bi[KC];
        #pragma unroll
        for (int u = 0; u < KC; u++) { bv[u] = -FLT_MAX; bi[u] = 0x7fffffff; }
        for (int c2 = 0; c2 < 32; c2++) {
            float2 e = mb[tid * 32 + c2];
            float s = e.x; int id = __float_as_int(e.y);
            if (better(s, id, bv[KC - 1], bi[KC - 1])) {
                int pos = KC - 1;
                while (pos > 0 && better(s, id, bv[pos - 1], bi[pos - 1])) {
                    bv[pos] = bv[pos - 1]; bi[pos] = bi[pos - 1]; pos--;
                }
                bv[pos] = s; bi[pos] = id;
            }
        }
        size_t base = ((size_t)(qBase + tid) * NSLOT + cslot) * KC;
        #pragma unroll
        for (int u = 0; u < KC; u++) {
            g_cv[base + u] = bv[u];
            g_ci[base + u] = (bi[u] < MPPAD) ? g_pidx[bi[u]] : MP;
        }
    }
}

// ---------------- s7 kernel: per-qblock prune threshold ----------------
__global__ void s7_kernel() {
    __shared__ float mn[256];
    const int b = blockIdx.x, tid = threadIdx.x;
    const int q = b * QTILE + tid;
    float top[KTOP];
    #pragma unroll
    for (int u = 0; u < KTOP; u++) top[u] = -FLT_MAX;
    for (int slotj = 0; slotj < NPA; slotj++) {
        size_t base = ((size_t)q * NSLOT + NCHB + slotj) * KC;
        for (int u = 0; u < KC; u++) {
            float v = g_cv[base + u];
            if (v > top[KTOP - 1]) {
                int pos = KTOP - 1;
                while (pos > 0 && v > top[pos - 1]) { top[pos] = top[pos - 1]; pos--; }
                top[pos] = v;
            }
        }
    }
    mn[tid] = top[KTOP - 1];
    __syncthreads();
    for (int o = 128; o > 0; o >>= 1) {
        if (tid < o) mn[tid] = fminf(mn[tid], mn[tid + o]);
        __syncthreads();
    }
    if (tid == 0) g_s7s[b] = mn[0] - 0.01f;
}

// ---------------- rescore: filter top-32 + exact fp32 ----------------
#define TOT (NSLOT * KC)              // 636
#define PERLANE ((TOT + 31) / 32)     // 20
__global__ __launch_bounds__(256)
void rescore_kernel(const float* __restrict__ pe,
                    const float* __restrict__ pt,
                    const float* __restrict__ lam) {
    __shared__ float qs[DIM];
    __shared__ int   sel[TOPC];
    __shared__ float scv[TOPC];
    const int q = blockIdx.x;
    const int tid = threadIdx.x, wid = tid >> 5, lane = tid & 31;
    qs[tid] = g_qn[q * DIM + tid];
    __syncthreads();

    if (wid == 0) {
        float cv[PERLANE]; int cix[PERLANE];
        #pragma unroll
        for (int j = 0; j < PERLANE; j++) {
            int c = lane * PERLANE + j;
            if (c < TOT) {
                cv[j]  = g_cv[(size_t)q * TOT + c];
                cix[j] = g_ci[(size_t)q * TOT + c];
            } else { cv[j] = -FLT_MAX; cix[j] = 0x7fffffff; }
        }
        for (int u = 0; u < TOPC; u++) {
            float lv = cv[0]; int lix = cix[0]; int lsl = 0;
            #pragma unroll
            for (int j = 1; j < PERLANE; j++)
                if (better(cv[j], cix[j], lv, lix)) { lv = cv[j]; lix = cix[j]; lsl = j; }
            int lpos = lane * PERLANE + lsl;
            #pragma unroll
            for (int o = 16; o > 0; o >>= 1) {
                float ov = __shfl_xor_sync(0xffffffff, lv, o);
                int   oi = __shfl_xor_sync(0xffffffff, lix, o);
                int   op = __shfl_xor_sync(0xffffffff, lpos, o);
                if (better(ov, oi, lv, lix)) { lv = ov; lix = oi; lpos = op; }
            }
            if (lane == 0) sel[u] = lix;
            if ((lpos / PERLANE) == lane) cv[lpos % PERLANE] = -FLT_MAX, cix[lpos % PERLANE] = 0x7fffffff;
        }
    }
    __syncthreads();

    const float tq = g_qts[q];
    const float lv = lam[0];
    for (int r = 0; r < 4; r++) {
        int c = wid + 8 * r;
        if (c >= TOPC) break;
        int idx = sel[c];
        float s = -FLT_MAX;
        if (idx < MP) {
            const float4* pp = (const float4*)(pe + (size_t)idx * DIM) + lane * 2;
            const float4* qq = (const float4*)qs + lane * 2;
            float4 v0 = pp[0], v1 = pp[1], q0 = qq[0], q1 = qq[1];
            float acc = v0.x*q0.x + v0.y*q0.y + v0.z*q0.z + v0.w*q0.w
                      + v1.x*q1.x + v1.y*q1.y + v1.z*q1.z + v1.w*q1.w;
            float ss = v0.x*v0.x + v0.y*v0.y + v0.z*v0.z + v0.w*v0.w
                     + v1.x*v1.x + v1.y*v1.y + v1.z*v1.z + v1.w*v1.w;
            #pragma unroll
            for (int o = 16; o > 0; o >>= 1) {
                acc += __shfl_xor_sync(0xffffffff, acc, o);
                ss  += __shfl_xor_sync(0xffffffff, ss, o);
            }
            s = acc / fmaxf(sqrtf(ss), 1e-8f) * expf(-lv * fabsf(tq - pt[idx]));
        }
        if (lane == 0) scv[c] = s;
    }
    __syncthreads();
    if (tid == 0) {
        float bv[KTOP]; int bi[KTOP];
        #pragma unroll
        for (int u = 0; u < KTOP; u++) { bv[u] = -FLT_MAX; bi[u] = 0x7fffffff; }
        for (int c = 0; c < TOPC; c++) {
            float s = scv[c]; int id = sel[c];
            if (id < MP && better(s, id, bv[KTOP - 1], bi[KTOP - 1])) {
                int pos = KTOP - 1;
                while (pos > 0 && better(s, id, bv[pos - 1], bi[pos - 1])) {
                    bv[pos] = bv[pos - 1]; bi[pos] = bi[pos - 1]; pos--;
                }
                bv[pos] = s; bi[pos] = id;
            }
        }
        #pragma unroll
        for (int u = 0; u < KTOP; u++) g_topi[q * KTOP + u] = bi[u];
    }
}

// ---------------- finalize ----------------
__global__ __launch_bounds__(256)
void finalize_kernel(const float* __restrict__ qe,
                     const float* __restrict__ pool,
                     const float* __restrict__ W,
                     const float* __restrict__ bvec,
                     float* __restrict__ out) {
    int q = blockIdx.x;
    int d = threadIdx.x;
    __shared__ float vsh[DIM];
    __shared__ float red[3][8];

    const float cw0 = 1.70710678f;
    const float cw6 = 0.5f;
    const int oq = g_qsrc[q];

    float acc = 0.0f;
    #pragma unroll
    for (int k = 0; k < KTOP; k++) {
        int id = g_topi[q * KTOP + k];
        float c = (k == 0) ? cw0 : ((k == 6) ? cw6 : 1.0f);
        acc += c * pool[(size_t)id * DIM + d];
    }
    vsh[d] = acc;
    __syncthreads();

    float f = 0.0f;
    #pragma unroll 8
    for (int j = 0; j < DIM; j++) f += vsh[j] * W[j * DIM + d];
    f = f * (1.0f / 7.0f) + bvec[d];

    float qnv = g_qn[q * DIM + d];
    float qev = qe[(size_t)oq * DIM + d];
    float ff = f * f;
    float qf = qnv * f;
    float dd = (qev - f) * (qev - f);

    #pragma unroll
    for (int o = 16; o > 0; o >>= 1) {
        ff += __shfl_xor_sync(0xffffffff, ff, o);
        qf += __shfl_xor_sync(0xffffffff, qf, o);
        dd += __shfl_xor_sync(0xffffffff, dd, o);
    }
    int lane = d & 31, w = d >> 5;
    if (lane == 0) { red[0][w] = ff; red[1][w] = qf; red[2][w] = dd; }
    __syncthreads();
    if (d == 0) {
        float FF = 0, QF = 0, DD = 0;
        #pragma unroll
        for (int i = 0; i < 8; i++) { FF += red[0][i]; QF += red[1][i]; DD += red[2][i]; }
        float nf   = sqrtf(FF);
        float cosv = QF / fmaxf(nf, 1e-8f);
        out[oq] = 0.6f * (1.0f - cosv) + 0.4f * sqrtf(DD);
    }
}

// ---------------- launcher ----------------
extern "C" void kernel_launch(void* const* d_in, const int* in_sizes, int n_in,
                              void* d_out, int out_size) {
    const float* qe  = (const float*)d_in[0];
    const float* qt  = (const float*)d_in[1];
    const float* pe  = (const float*)d_in[2];
    const float* pt  = (const float*)d_in[3];
    const float* lam = (const float*)d_in[4];
    const float* W   = (const float*)d_in[5];
    const float* b   = (const float*)d_in[6];
    float* out = (float*)d_out;

    static int configured = 0;
    if (!configured) {
        cudaFuncSetAttribute(engine_kernel,
                             cudaFuncAttributeMaxDynamicSharedMemorySize, SMEM_TOTAL);
        configured = 1;
    }

    zero_kernel<<<1, 1024>>>();
    qsort_kernel<<<1, 1024>>>(qt);
    prep_query_kernel<<<NQ / 8, 256>>>(qe, lam);
    hist_kernel<<<(MP + 1023) / 1024, 1024>>>(pt);
    scan_kernel<<<1, 1024>>>();
    scatter_kernel<<<(MP + 1023) / 1024, 1024>>>(pt);
    prep_pool_kernel<<<(MPPAD + 7) / 8, 256>>>(pe, pt, lam);
    engine_kernel<<<dim3(NPA, NQB), 512, SMEM_TOTAL>>>(0);    // phase A
    s7_kernel<<<NQB, 256>>>();
    buildlist_kernel<<<NQB, 256>>>(lam);
    engine_kernel<<<dim3(NCHB, NQB), 512, SMEM_TOTAL>>>(1);   // phase B (148 CTAs, balanced)
    rescore_kernel<<<NQ, 256>>>(pe, pt, lam);
    finalize_kernel<<<NQ, 256>>>(qe, pe, W, b, out);
}

// round 15
// speedup vs baseline: 1.4301x; 1.4301x over previous
#include <cuda_runtime.h>
#include <cuda_bf16.h>
#include <math.h>
#include <float.h>
#include <stdint.h>

#define NQ    1024
#define MP    100000
#define DIM   256
#define KTOP  7
#define QTILE 256
#define PTILE 128
#define NT    782            // ceil(100000/128)
#define NCH   37             // grid = 4 x 37 = 148 CTAs (one wave)
#define KC    12             // candidates per (q, chunk)
#define TOPC  24             // global approx filter size before exact rescore
#define MPPAD (NT*PTILE)     // 100096

// ---------------- device scratch ----------------
__device__ float g_qn[NQ * DIM];
__device__ float g_eq[NQ];
__device__ float g_ieq[NQ];
__device__ float g_pA[MPPAD];   // pinv * exp(-l*pt)
__device__ float g_pB[MPPAD];   // pinv * exp(+l*pt)
__device__ __nv_bfloat16 g_qhi[NQ * DIM];
__device__ __nv_bfloat16 g_phi[(size_t)MPPAD * DIM];
__device__ float g_cv[(size_t)NQ * NCH * KC];
__device__ int   g_ci[(size_t)NQ * NCH * KC];

__device__ __forceinline__ bool better(float s1, int i1, float s2, int i2) {
    return (s1 > s2) || (s1 == s2 && i1 < i2);
}

__device__ __forceinline__ uint32_t smem_to_u32(const void* p) {
    uint32_t a;
    asm("{ .reg .u64 t; cvta.to.shared.u64 t, %1; cvt.u32.u64 %0, t; }" : "=r"(a) : "l"(p));
    return a;
}
__device__ __forceinline__ void ldsm_x4(uint32_t& r0, uint32_t& r1, uint32_t& r2, uint32_t& r3,
                                        uint32_t addr) {
    asm volatile("ldmatrix.sync.aligned.m8n8.x4.shared.b16 {%0,%1,%2,%3}, [%4];"
        : "=r"(r0), "=r"(r1), "=r"(r2), "=r"(r3) : "r"(addr));
}
__device__ __forceinline__ void mma16816(float* d, const uint32_t* a, uint32_t b0, uint32_t b1) {
    asm volatile("mma.sync.aligned.m16n8k16.row.col.f32.bf16.bf16.f32 "
        "{%0,%1,%2,%3}, {%4,%5,%6,%7}, {%8,%9}, {%0,%1,%2,%3};"
        : "+f"(d[0]), "+f"(d[1]), "+f"(d[2]), "+f"(d[3])
        : "r"(a[0]), "r"(a[1]), "r"(a[2]), "r"(a[3]), "r"(b0), "r"(b1));
}
#define CP_ASYNC16(dst, src) asm volatile("cp.async.cg.shared.global [%0], [%1], 16;" :: "r"(dst), "l"(src))
#define CP_COMMIT() asm volatile("cp.async.commit_group;" ::: "memory")
#define CP_WAIT0()  asm volatile("cp.async.wait_group 0;" ::: "memory")

// top-3 sorted insertion (hot path: one compare)
__device__ __forceinline__ void ins3(float s, int p,
                                     float& v0, int& i0, float& v1, int& i1,
                                     float& v2, int& i2) {
    if (better(s, p, v2, i2)) {
        if (better(s, p, v1, i1)) {
            v2 = v1; i2 = i1;
            if (better(s, p, v0, i0)) { v1 = v0; i1 = i0; v0 = s; i0 = p; }
            else { v1 = s; i1 = p; }
        } else { v2 = s; i2 = p; }
    }
}

// smem layout
#define SOFF_A    0                  // 131072: A 256x256 bf16, swizzled 512B rows
#define SOFF_B0   131072             // 32768: B chunk 128p x 128k bf16 (256B rows)
#define SOFF_B1   163840             // 32768
#define SOFF_PAB  196608             // 1024: float2[128] = (pA, pB)
#define SMEM_TOTAL 197632

// ---------------- kernel 0: query prep ----------------
__global__ void prep_query_kernel(const float* __restrict__ qe,
                                  const float* __restrict__ qt,
                                  const float* __restrict__ lam) {
    int row  = blockIdx.x * 8 + (threadIdx.x >> 5);
    int lane = threadIdx.x & 31;
    if (row >= NQ) return;
    const float4* src = (const float4*)(qe + row * DIM + lane * 8);
    float4 a = src[0], b = src[1];
    float ss = a.x*a.x + a.y*a.y + a.z*a.z + a.w*a.w
             + b.x*b.x + b.y*b.y + b.z*b.z + b.w*b.w;
    #pragma unroll
    for (int o = 16; o > 0; o >>= 1) ss += __shfl_xor_sync(0xffffffff, ss, o);
    float inv = 1.0f / fmaxf(sqrtf(ss), 1e-8f);
    float v[8] = {a.x*inv, a.y*inv, a.z*inv, a.w*inv, b.x*inv, b.y*inv, b.z*inv, b.w*inv};
    float4* dst = (float4*)(g_qn + row * DIM + lane * 8);
    dst[0] = make_float4(v[0], v[1], v[2], v[3]);
    dst[1] = make_float4(v[4], v[5], v[6], v[7]);
    __nv_bfloat16 hv[8];
    #pragma unroll
    for (int i = 0; i < 8; i++) hv[i] = __float2bfloat16(v[i]);
    *(uint4*)(g_qhi + row * DIM + lane * 8) = *(uint4*)hv;
    if (lane == 0) {
        float l = lam[0], t = qt[row];
        g_eq[row]  = expf(l * t);
        g_ieq[row] = expf(-l * t);
    }
}

// ---------------- kernel 1: pool prep (padded to MPPAD) ----------------
__global__ void prep_pool_kernel(const float* __restrict__ pe,
                                 const float* __restrict__ pt,
                                 const float* __restrict__ lam) {
    int row  = blockIdx.x * 8 + (threadIdx.x >> 5);
    int lane = threadIdx.x & 31;
    if (row >= MPPAD) return;
    if (row >= MP) {
        *(uint4*)(g_phi + (size_t)row * DIM + lane * 8) = make_uint4(0, 0, 0, 0);
        if (lane == 0) { g_pA[row] = 0.f; g_pB[row] = 0.f; }
        return;
    }
    const float4* src = (const float4*)(pe + (size_t)row * DIM + lane * 8);
    float4 a = src[0], b = src[1];
    float ss = a.x*a.x + a.y*a.y + a.z*a.z + a.w*a.w
             + b.x*b.x + b.y*b.y + b.z*b.z + b.w*b.w;
    #pragma unroll
    for (int o = 16; o > 0; o >>= 1) ss += __shfl_xor_sync(0xffffffff, ss, o);
    float v[8] = {a.x, a.y, a.z, a.w, b.x, b.y, b.z, b.w};
    __nv_bfloat16 hv[8];
    #pragma unroll
    for (int i = 0; i < 8; i++) hv[i] = __float2bfloat16(v[i]);
    *(uint4*)(g_phi + (size_t)row * DIM + lane * 8) = *(uint4*)hv;
    if (lane == 0) {
        float inv = 1.0f / fmaxf(sqrtf(ss), 1e-8f);
        float l = lam[0], t = pt[row];
        g_pA[row] = inv * expf(-l * t);
        g_pB[row] = inv * expf(l * t);
    }
}

// ---------------- kernel 2: HMMA GEMM (512 thr, 256q x 128p tiles) ----------------
__global__ __launch_bounds__(512, 1)
void main_topk_kernel() {
    extern __shared__ char smem[];
    const uint32_t sb = smem_to_u32(smem);
    float2* spAB = (float2*)(smem + SOFF_PAB);

    const int tid = threadIdx.x;
    const int wid = tid >> 5, lane = tid & 31;
    const int wq = wid >> 1, wp = wid & 1;     // 8q x 2p warps, warp tile 32q x 64p
    const int qBase = blockIdx.x * QTILE;
    const int ch = blockIdx.y;
    const int tile0   = (ch * NT) / NCH;
    const int tileEnd = ((ch + 1) * NT) / NCH;
    const int NCHK = (tileEnd - tile0) * 2;    // 128k chunks total

    // ---- load A once (256 rows x 512B, swizzled): 2 threads/row ----
    {
        int row = tid >> 1, part = tid & 1;
        const uint4* asrc = (const uint4*)(g_qhi + (size_t)(qBase + row) * DIM) + part * 16;
        uint32_t arb = (uint32_t)row * 512;
        uint32_t xr0 = (uint32_t)(row & 7) << 4;
        #pragma unroll
        for (int g2 = 0; g2 < 16; g2++) {
            uint32_t kg = (uint32_t)(part * 16 + g2);
            *(uint4*)(smem + SOFF_A + arb + ((kg << 4) ^ xr0)) = asrc[g2];
        }
    }

    // per-thread row weights (4 rows, fixed all kernel)
    const int g = lane >> 2;
    float eqr[4], ieqr[4];
    #pragma unroll
    for (int mt = 0; mt < 2; mt++)
        #pragma unroll
        for (int h = 0; h < 2; h++) {
            int r = qBase + wq * 32 + mt * 16 + g + h * 8;
            eqr[mt * 2 + h]  = g_eq[r];
            ieqr[mt * 2 + h] = g_ieq[r];
        }

    // fragment addressing
    const int mh = (lane >> 4) & 1;
    const int mlow = (lane >> 3) & 1;
    const int lr = lane & 7;
    const uint32_t xr = (uint32_t)lr << 4;
    uint32_t aBase[2], bBase[4];
    #pragma unroll
    for (int mt = 0; mt < 2; mt++)
        aBase[mt] = sb + SOFF_A + (uint32_t)(wq * 32 + mt * 16 + mlow * 8 + lr) * 512;
    #pragma unroll
    for (int n16 = 0; n16 < 4; n16++)
        bBase[n16] = (uint32_t)(wp * 64 + n16 * 16 + mlow * 8 + lr) * 256;

    // bucket top-3 per (thread, row)
    float tv0[4], tv1[4], tv2[4]; int ti0[4], ti1[4], ti2[4];
    #pragma unroll
    for (int j = 0; j < 4; j++) {
        tv0[j] = tv1[j] = tv2[j] = -FLT_MAX;
        ti0[j] = ti1[j] = ti2[j] = 0x7fffffff;
    }

    // cp.async for chunk s (128p x 128k = 32KB): 4 threads/row, 4 x 16B each
    const int brow = tid >> 2, bseg = tid & 3;
    const uint32_t brb = (uint32_t)brow * 256;
    const uint32_t bxr = (uint32_t)(brow & 7) << 4;
    #define ISSUE(s_) do { \
        int _t = tile0 + ((s_) >> 1), _kh = (s_) & 1; \
        const char* _src = (const char*)(g_phi + (size_t)(_t * PTILE + brow) * DIM + _kh * 128 + bseg * 32); \
        uint32_t _dst = sb + (((s_) & 1) ? SOFF_B1 : SOFF_B0); \
        _Pragma("unroll") \
        for (int _g = 0; _g < 4; _g++) { \
            uint32_t _kg = (uint32_t)(bseg * 4 + _g); \
            CP_ASYNC16(_dst + brb + ((_kg << 4) ^ bxr), _src + _g * 16); \
        } \
        CP_COMMIT(); \
    } while (0)

    ISSUE(0);

    float d[2][8][4];

    #pragma unroll 1
    for (int t = tile0; t < tileEnd; t++) {
        const int pBase = t * PTILE;
        #pragma unroll
        for (int mt = 0; mt < 2; mt++)
            #pragma unroll
            for (int n = 0; n < 8; n++)
                #pragma unroll
                for (int e = 0; e < 4; e++) d[mt][n][e] = 0.0f;

        #pragma unroll
        for (int c = 0; c < 2; c++) {
            const int s = (t - tile0) * 2 + c;
            CP_WAIT0();
            __syncthreads();   // chunk s visible to all; also fences buffer (s+1)&1 reuse
            if (c == 0 && tid < 128)
                spAB[tid] = make_float2(g_pA[pBase + tid], g_pB[pBase + tid]);
            if (s + 1 < NCHK) ISSUE(s + 1);

            const uint32_t bbuf = sb + ((s & 1) ? SOFF_B1 : SOFF_B0);
            #pragma unroll
            for (int kk = 0; kk < 8; kk++) {
                const int ks = c * 8 + kk;
                uint32_t a[2][4];
                uint32_t aoffk = ((uint32_t)((ks * 2 + mh) << 4)) ^ xr;
                ldsm_x4(a[0][0], a[0][1], a[0][2], a[0][3], aBase[0] + aoffk);
                ldsm_x4(a[1][0], a[1][1], a[1][2], a[1][3], aBase[1] + aoffk);
                uint32_t boffk = ((uint32_t)((kk * 2 + mh) << 4)) ^ xr;
                #pragma unroll
                for (int n16 = 0; n16 < 4; n16++) {
                    uint32_t b0, b1, b2, b3;
                    ldsm_x4(b0, b1, b2, b3, bbuf + bBase[n16] + boffk);
                    mma16816(d[0][n16 * 2 + 0], a[0], b0, b2);
                    mma16816(d[0][n16 * 2 + 1], a[0], b1, b3);
                    mma16816(d[1][n16 * 2 + 0], a[1], b0, b2);
                    mma16816(d[1][n16 * 2 + 1], a[1], b1, b3);
                }
            }
        }

        // ---- in-register epilogue: weight + bucket top-3 ----
        #pragma unroll
        for (int n = 0; n < 8; n++) {
            int c0 = wp * 64 + n * 8 + (lane & 3) * 2;
            float4 w = *(const float4*)((const char*)spAB + (size_t)c0 * 8);
            int p0 = pBase + c0;
            bool ok0 = (p0 < MP), ok1 = (p0 + 1 < MP);
            #pragma unroll
            for (int mt = 0; mt < 2; mt++) {
                const int j0 = mt * 2, j1 = mt * 2 + 1;
                float s00 = d[mt][n][0] * fminf(eqr[j0] * w.x, ieqr[j0] * w.y);
                float s01 = d[mt][n][1] * fminf(eqr[j0] * w.z, ieqr[j0] * w.w);
                float s10 = d[mt][n][2] * fminf(eqr[j1] * w.x, ieqr[j1] * w.y);
                float s11 = d[mt][n][3] * fminf(eqr[j1] * w.z, ieqr[j1] * w.w);
                if (ok0) {
                    ins3(s00, p0, tv0[j0], ti0[j0], tv1[j0], ti1[j0], tv2[j0], ti2[j0]);
                    ins3(s10, p0, tv0[j1], ti0[j1], tv1[j1], ti1[j1], tv2[j1], ti2[j1]);
                }
                if (ok1) {
                    ins3(s01, p0 + 1, tv0[j0], ti0[j0], tv1[j0], ti1[j0], tv2[j0], ti2[j0]);
                    ins3(s11, p0 + 1, tv0[j1], ti0[j1], tv1[j1], ti1[j1], tv2[j1], ti2[j1]);
                }
            }
        }
    }

    // ---- final merge: 8 buckets x 3 per row -> top-12 per (q, chunk) ----
    __syncthreads();   // all epilogues done before aliasing B buffers
    float2* mb = (float2*)(smem + SOFF_B0);   // [256 rows][8 slots][3] = 48KB
    const int slot = wp * 4 + (lane & 3);
    #pragma unroll
    for (int mt = 0; mt < 2; mt++)
        #pragma unroll
        for (int h = 0; h < 2; h++) {
            int r = wq * 32 + mt * 16 + g + h * 8;
            int j = mt * 2 + h;
            int base = (r * 8 + slot) * 3;
            mb[base + 0] = make_float2(tv0[j], __int_as_float(ti0[j]));
            mb[base + 1] = make_float2(tv1[j], __int_as_float(ti1[j]));
            mb[base + 2] = make_float2(tv2[j], __int_as_float(ti2[j]));
        }
    __syncthreads();
    if (tid < 256) {
        float bv[KC]; int bi[KC];
        #pragma unroll
        for (int u = 0; u < KC; u++) { bv[u] = -FLT_MAX; bi[u] = 0x7fffffff; }
        for (int c2 = 0; c2 < 24; c2++) {
            float2 e = mb[tid * 24 + c2];
            float s = e.x; int id = __float_as_int(e.y);
            if (better(s, id, bv[KC - 1], bi[KC - 1])) {
                int pos = KC - 1;
                while (pos > 0 && better(s, id, bv[pos - 1], bi[pos - 1])) {
                    bv[pos] = bv[pos - 1]; bi[pos] = bi[pos - 1]; pos--;
                }
                bv[pos] = s; bi[pos] = id;
            }
        }
        size_t base = ((size_t)(qBase + tid) * NCH + ch) * KC;
        #pragma unroll
        for (int u = 0; u < KC; u++) { g_cv[base + u] = bv[u]; g_ci[base + u] = bi[u]; }
    }
}

// ---------------- kernel 3: fused filter(top-24) + exact rescore + GCN + score ----------------
#define TOT (NCH * KC)              // 444
#define PERLANE ((TOT + 31) / 32)   // 14
__global__ __launch_bounds__(256)
void rescore_finalize_kernel(const float* __restrict__ qe,
                             const float* __restrict__ pe,
                             const float* __restrict__ W,
                             const float* __restrict__ bvec,
                             float* __restrict__ out) {
    __shared__ float qs[DIM];
    __shared__ int   sel[TOPC];
    __shared__ float scv[TOPC];
    __shared__ int   topi[KTOP];
    __shared__ float vsh[DIM];
    __shared__ float red[3][8];
    const int q = blockIdx.x;
    const int tid = threadIdx.x, wid = tid >> 5, lane = tid & 31;
    qs[tid] = g_qn[q * DIM + tid];
    __syncthreads();

    // warp 0: iterative argmax extraction of approx top-24
    if (wid == 0) {
        float cv[PERLANE]; int cix[PERLANE];
        #pragma unroll
        for (int j = 0; j < PERLANE; j++) {
            int c = lane * PERLANE + j;
            if (c < TOT) {
                cv[j]  = g_cv[(size_t)q * TOT + c];
                cix[j] = g_ci[(size_t)q * TOT + c];
            } else { cv[j] = -FLT_MAX; cix[j] = 0x7fffffff; }
        }
        for (int u = 0; u < TOPC; u++) {
            float lv = cv[0]; int lix = cix[0]; int lsl = 0;
            #pragma unroll
            for (int j = 1; j < PERLANE; j++)
                if (better(cv[j], cix[j], lv, lix)) { lv = cv[j]; lix = cix[j]; lsl = j; }
            int lpos = lane * PERLANE + lsl;
            #pragma unroll
            for (int o = 16; o > 0; o >>= 1) {
                float ov = __shfl_xor_sync(0xffffffff, lv, o);
                int   oi = __shfl_xor_sync(0xffffffff, lix, o);
                int   op = __shfl_xor_sync(0xffffffff, lpos, o);
                if (better(ov, oi, lv, lix)) { lv = ov; lix = oi; lpos = op; }
            }
            if (lane == 0) { sel[u] = lix; }
            if ((lpos / PERLANE) == lane) cv[lpos % PERLANE] = -FLT_MAX, cix[lpos % PERLANE] = 0x7fffffff;
        }
    }
    __syncthreads();

    // exact fp32 rescore of the 24 candidates (one warp per candidate, 3 rounds)
    const float eqv = g_eq[q], ieqv = g_ieq[q];
    for (int r = 0; r < 3; r++) {
        int c = wid + 8 * r;
        if (c >= TOPC) break;
        int idx = sel[c];
        float s = -FLT_MAX;
        if (idx < MP) {
            const float4* pp = (const float4*)(pe + (size_t)idx * DIM) + lane * 2;
            const float4* qq = (const float4*)qs + lane * 2;
            float4 v0 = pp[0], v1 = pp[1], q0 = qq[0], q1 = qq[1];
            float acc = v0.x*q0.x + v0.y*q0.y + v0.z*q0.z + v0.w*q0.w
                      + v1.x*q1.x + v1.y*q1.y + v1.z*q1.z + v1.w*q1.w;
            #pragma unroll
            for (int o = 16; o > 0; o >>= 1) acc += __shfl_xor_sync(0xffffffff, acc, o);
            s = acc * fminf(eqv * g_pA[idx], ieqv * g_pB[idx]);
        }
        if (lane == 0) scv[c] = s;
    }
    __syncthreads();
    if (tid == 0) {
        float bv[KTOP]; int bi[KTOP];
        #pragma unroll
        for (int u = 0; u < KTOP; u++) { bv[u] = -FLT_MAX; bi[u] = 0x7fffffff; }
        for (int c = 0; c < TOPC; c++) {
            float s = scv[c]; int id = sel[c];
            if (id < MP && better(s, id, bv[KTOP - 1], bi[KTOP - 1])) {
                int pos = KTOP - 1;
                while (pos > 0 && better(s, id, bv[pos - 1], bi[pos - 1])) {
                    bv[pos] = bv[pos - 1]; bi[pos] = bi[pos - 1]; pos--;
                }
                bv[pos] = s; bi[pos] = id;
            }
        }
        #pragma unroll
        for (int u = 0; u < KTOP; u++) topi[u] = bi[u];
    }
    __syncthreads();

    // ---- GCN epilogue + anomaly score ----
    const float cw0 = 1.70710678f;  // 1 + 1/sqrt(2)
    const float cw6 = 0.5f;
    const int d = tid;

    float acc = 0.0f;
    #pragma unroll
    for (int k = 0; k < KTOP; k++) {
        int id = topi[k];
        float c = (k == 0) ? cw0 : ((k == 6) ? cw6 : 1.0f);
        acc += c * pe[(size_t)id * DIM + d];
    }
    vsh[d] = acc;
    __syncthreads();

    float f = 0.0f;
    #pragma unroll 8
    for (int j = 0; j < DIM; j++) f += vsh[j] * W[j * DIM + d];
    f = f * (1.0f / 7.0f) + bvec[d];

    float qnv = qs[d];
    float qev = qe[(size_t)q * DIM + d];
    float ff = f * f;
    float qf = qnv * f;
    float dd = (qev - f) * (qev - f);

    #pragma unroll
    for (int o = 16; o > 0; o >>= 1) {
        ff += __shfl_xor_sync(0xffffffff, ff, o);
        qf += __shfl_xor_sync(0xffffffff, qf, o);
        dd += __shfl_xor_sync(0xffffffff, dd, o);
    }
    int w = d >> 5;
    if (lane == 0) { red[0][w] = ff; red[1][w] = qf; red[2][w] = dd; }
    __syncthreads();
    if (d == 0) {
        float FF = 0, QF = 0, DD = 0;
        #pragma unroll
        for (int i = 0; i < 8; i++) { FF += red[0][i]; QF += red[1][i]; DD += red[2][i]; }
        float nf   = sqrtf(FF);
        float cosv = QF / fmaxf(nf, 1e-8f);
        out[q] = 0.6f * (1.0f - cosv) + 0.4f * sqrtf(DD);
    }
}

// ---------------- launcher ----------------
extern "C" void kernel_launch(void* const* d_in, const int* in_sizes, int n_in,
                              void* d_out, int out_size) {
    const float* qe  = (const float*)d_in[0];
    const float* qt  = (const float*)d_in[1];
    const float* pe  = (const float*)d_in[2];
    const float* pt  = (const float*)d_in[3];
    const float* lam = (const float*)d_in[4];
    const float* W   = (const float*)d_in[5];
    const float* b   = (const float*)d_in[6];
    float* out = (float*)d_out;

    static int configured = 0;
    if (!configured) {
        cudaFuncSetAttribute(main_topk_kernel,
                             cudaFuncAttributeMaxDynamicSharedMemorySize, SMEM_TOTAL);
        configured = 1;
    }

    prep_query_kernel<<<NQ / 8, 256>>>(qe, qt, lam);
    prep_pool_kernel<<<(MPPAD + 7) / 8, 256>>>(pe, pt, lam);
    dim3 grid(NQ / QTILE, NCH);
    main_topk_kernel<<<grid, 512, SMEM_TOTAL>>>();
    rescore_finalize_kernel<<<NQ, 256>>>(qe, pe, W, b, out);
}